// round 2
// baseline (speedup 1.0000x reference)
#include <cuda_runtime.h>
#include <cstdint>

#define BB 4
#define NN 8192
#define NP 2048
#define CC 64
#define NS 32
#define R2 0.01f
#define NSLOT 33
#define GPB (NP * NSLOT)   // 67584 group-slots per batch

// Scratch (no cudaMalloc allowed)
__device__ float g_featT[BB * NN * CC];    // features transposed to (B, N, C)
__device__ int   g_idx[BB * NP * NSLOT];   // ball-query result incl. fps slot

typedef unsigned long long u64;

// ---------------- packed f32x2 helpers ----------------
__device__ __forceinline__ u64 pk2(float lo, float hi) {
    u64 r; asm("mov.b64 %0, {%1, %2};" : "=l"(r) : "f"(lo), "f"(hi)); return r;
}
__device__ __forceinline__ void upk2(u64 v, float& lo, float& hi) {
    asm("mov.b64 {%0, %1}, %2;" : "=f"(lo), "=f"(hi) : "l"(v));
}
__device__ __forceinline__ u64 addx2(u64 a, u64 b) {
    u64 r; asm("add.rn.f32x2 %0, %1, %2;" : "=l"(r) : "l"(a), "l"(b)); return r;
}
__device__ __forceinline__ u64 mulx2(u64 a, u64 b) {
    u64 r; asm("mul.rn.f32x2 %0, %1, %2;" : "=l"(r) : "l"(a), "l"(b)); return r;
}
__device__ __forceinline__ u64 fmax2(u64 a, u64 b, u64 c) {
    u64 r; asm("fma.rn.f32x2 %0, %1, %2, %3;" : "=l"(r) : "l"(a), "l"(b), "l"(c)); return r;
}

// ---------------- K1: transpose features (B,C,N) -> (B,N,C) ----------------
__global__ __launch_bounds__(256) void transpose_kernel(const float* __restrict__ feat) {
    __shared__ float tile[32][33];
    int b  = blockIdx.z;
    int n0 = blockIdx.x * 32;
    int c0 = blockIdx.y * 32;
    int tx = threadIdx.x, ty = threadIdx.y;  // block (32, 8)
    #pragma unroll
    for (int i = 0; i < 32; i += 8)
        tile[ty + i][tx] = feat[((size_t)(b * CC + c0 + ty + i)) * NN + n0 + tx];
    __syncthreads();
    #pragma unroll
    for (int i = 0; i < 32; i += 8)
        g_featT[((size_t)b * NN + n0 + ty + i) * CC + c0 + tx] = tile[tx][ty + i];
}

// ---------------- K2: ball query ----------------
// 4 warps/block, 8 centroids/warp (held in registers), packed f32x2 distance math.
// Points staged (negated) into smem in tiles of 1024; each warp evaluates each
// pair-of-points against all 8 of its centroids -> 8x operand reuse in regs.
#define BQ_WARPS 4
#define BQ_M 8
#define BQ_CPB (BQ_WARPS * BQ_M)   // 32 centroids per block
#define TILE_PTS 1024
#define TILE_PAIRS (TILE_PTS / 2)

__global__ __launch_bounds__(128) void bq_kernel(const float* __restrict__ xyz,
                                                 const float* __restrict__ new_xyz,
                                                 const int* __restrict__ fps_idx) {
    __shared__ u64 sx[TILE_PAIRS], sy[TILE_PAIRS], sz[TILE_PAIRS];
    __shared__ int slist[BQ_CPB][NS];

    int warpId = threadIdx.x >> 5;
    int lane   = threadIdx.x & 31;
    int cbase  = blockIdx.x * BQ_CPB + warpId * BQ_M;  // global centroid id base
    int b      = cbase / NP;                           // uniform per block (NP % BQ_CPB == 0)

    u64 qx2[BQ_M], qy2[BQ_M], qz2[BQ_M];
    int cnt[BQ_M];
    #pragma unroll
    for (int m = 0; m < BQ_M; m++) {
        int p = (cbase + m) - b * NP;
        const float* q = new_xyz + ((size_t)b * NP + p) * 3;
        float qx = q[0], qy = q[1], qz = q[2];
        qx2[m] = pk2(qx, qx); qy2[m] = pk2(qy, qy); qz2[m] = pk2(qz, qz);
        cnt[m] = 0;
    }

    const float* xb = xyz + (size_t)b * NN * 3;

    for (int tilebase = 0; tilebase < NN; tilebase += TILE_PTS) {
        // stage points, negated, interleaved into f32x2 pairs
        for (int i = threadIdx.x; i < TILE_PTS; i += 128) {
            const float* xp = xb + (size_t)(tilebase + i) * 3;
            ((float*)sx)[i] = -xp[0];
            ((float*)sy)[i] = -xp[1];
            ((float*)sz)[i] = -xp[2];
        }
        __syncthreads();

        bool active = false;
        #pragma unroll
        for (int m = 0; m < BQ_M; m++) active |= (cnt[m] < NS);

        if (active) {
            for (int sub = 0; sub < TILE_PAIRS / 32; sub++) {
                int j = sub * 32 + lane;
                u64 px = sx[j], py = sy[j], pz = sz[j];
                int pi0 = tilebase + 2 * j;   // even point index of this lane's pair
                #pragma unroll
                for (int m = 0; m < BQ_M; m++) {
                    if (cnt[m] >= NS) continue;   // warp-uniform
                    u64 dx = addx2(qx2[m], px);   // q - p (points pre-negated)
                    u64 dy = addx2(qy2[m], py);
                    u64 dz = addx2(qz2[m], pz);
                    u64 d2 = fmax2(dx, dx, fmax2(dy, dy, mulx2(dz, dz)));
                    float d0, d1; upk2(d2, d0, d1);
                    unsigned m0 = __ballot_sync(0xffffffffu, d0 < R2);
                    unsigned m1 = __ballot_sync(0xffffffffu, d1 < R2);
                    if (m0 | m1) {
                        unsigned lt = (1u << lane) - 1u;
                        int lc = warpId * BQ_M + m;
                        int c0 = cnt[m] + __popc(m0 & lt) + __popc(m1 & lt);
                        if (((m0 >> lane) & 1) && c0 < NS) slist[lc][c0] = pi0;
                        int c1 = c0 + ((m0 >> lane) & 1);
                        if (((m1 >> lane) & 1) && c1 < NS) slist[lc][c1] = pi0 + 1;
                        cnt[m] += __popc(m0) + __popc(m1);
                    }
                }
            }
        }
        __syncthreads();
    }

    __syncwarp();
    #pragma unroll
    for (int m = 0; m < BQ_M; m++) {
        int lc = warpId * BQ_M + m;
        int ci = cbase + m;
        int cn = cnt[m] < NS ? cnt[m] : NS;
        int base = ci * NSLOT;
        if (lane == 0) g_idx[base] = fps_idx[ci];
        int pad = (cn > 0) ? slist[lc][0] : 0;
        int v = (lane < cn) ? slist[lc][lane] : pad;
        g_idx[base + 1 + lane] = v;
    }
}

// ---------------- K3: gather + write output ----------------
// Block handles 64 group-slots. Gathers 256B-contiguous feature columns from
// g_featT (coalesced), transposes through smem, writes out fully coalesced.
__global__ __launch_bounds__(256) void group_kernel(const float* __restrict__ xyz,
                                                    const float* __restrict__ new_xyz,
                                                    float* __restrict__ out) {
    __shared__ float sfeat[64][65];
    __shared__ int   sidx[64];
    __shared__ float scent[3][64];

    int b  = blockIdx.y;
    int g0 = blockIdx.x * 64;
    int t  = threadIdx.x;

    if (t < 64) sidx[t] = g_idx[b * GPB + g0 + t];
    __syncthreads();

    if (t < 192) {   // 64 slots x 3 dims: centered xyz
        int s = t & 63, dim = t >> 6;
        int g = g0 + s;
        int p = g / NSLOT;
        int pi = sidx[s];
        scent[dim][s] = xyz[((size_t)b * NN + pi) * 3 + dim]
                      - new_xyz[((size_t)b * NP + p) * 3 + dim];
    }
    {   // feature gather: 4 threads per slot, 4x float4 each (256B contiguous per slot)
        int slot = t >> 2, part = t & 3;
        int pi = sidx[slot];
        const float4* src = (const float4*)(g_featT + ((size_t)b * NN + pi) * CC) + part * 4;
        #pragma unroll
        for (int k = 0; k < 4; k++) {
            float4 v = src[k];
            int cb = part * 16 + k * 4;
            sfeat[slot][cb + 0] = v.x;
            sfeat[slot][cb + 1] = v.y;
            sfeat[slot][cb + 2] = v.z;
            sfeat[slot][cb + 3] = v.w;
        }
    }
    __syncthreads();

    int s  = t & 63;
    int c0 = t >> 6;   // warp-uniform channel phase (0..3)
    size_t outb = (size_t)b * 70 * GPB + g0 + s;
    for (int cc = c0; cc < 70; cc += 4) {
        float v;
        if (cc < 6) v = scent[(cc < 3) ? cc : (cc - 3)][s];
        else        v = sfeat[s][cc - 6];
        out[outb + (size_t)cc * GPB] = v;
    }
}

// ---------------- launch ----------------
extern "C" void kernel_launch(void* const* d_in, const int* in_sizes, int n_in,
                              void* d_out, int out_size) {
    const float* xyz = nullptr;
    const float* new_xyz = nullptr;
    const float* features = nullptr;
    const int*   fps = nullptr;
    for (int i = 0; i < n_in; i++) {
        switch (in_sizes[i]) {
            case BB * NN * 3:  xyz      = (const float*)d_in[i]; break;
            case BB * NP * 3:  new_xyz  = (const float*)d_in[i]; break;
            case BB * CC * NN: features = (const float*)d_in[i]; break;
            case BB * NP:      fps      = (const int*)d_in[i];   break;
        }
    }
    transpose_kernel<<<dim3(NN / 32, CC / 32, BB), dim3(32, 8)>>>(features);
    bq_kernel<<<(BB * NP) / BQ_CPB, 128>>>(xyz, new_xyz, fps);
    group_kernel<<<dim3(GPB / 64, BB), 256>>>(xyz, new_xyz, (float*)d_out);
}

// round 4
// speedup vs baseline: 1.4072x; 1.4072x over previous
#include <cuda_runtime.h>
#include <cstdint>

#define BB 4
#define NN 8192
#define NP 2048
#define CC 64
#define NS 32
#define R2 0.01f
#define NSLOT 33
#define GPB (NP * NSLOT)   // 67584 group-slots per batch

// Scratch (no cudaMalloc allowed)
__device__ float g_featT[BB * NN * CC];    // features transposed to (B, N, C)
__device__ int   g_idx[BB * NP * NSLOT];   // ball-query result incl. fps slot

typedef unsigned long long u64;

// ---------------- packed f32x2 helpers ----------------
__device__ __forceinline__ u64 pk2(float lo, float hi) {
    u64 r; asm("mov.b64 %0, {%1, %2};" : "=l"(r) : "f"(lo), "f"(hi)); return r;
}
__device__ __forceinline__ void upk2(u64 v, float& lo, float& hi) {
    asm("mov.b64 {%0, %1}, %2;" : "=f"(lo), "=f"(hi) : "l"(v));
}
__device__ __forceinline__ u64 addx2(u64 a, u64 b) {
    u64 r; asm("add.rn.f32x2 %0, %1, %2;" : "=l"(r) : "l"(a), "l"(b)); return r;
}
__device__ __forceinline__ u64 mulx2(u64 a, u64 b) {
    u64 r; asm("mul.rn.f32x2 %0, %1, %2;" : "=l"(r) : "l"(a), "l"(b)); return r;
}
__device__ __forceinline__ u64 fmax2(u64 a, u64 b, u64 c) {
    u64 r; asm("fma.rn.f32x2 %0, %1, %2, %3;" : "=l"(r) : "l"(a), "l"(b), "l"(c)); return r;
}

// ---------------- K1: transpose features (B,C,N) -> (B,N,C), float4 both ways ----
__global__ __launch_bounds__(256) void transpose_kernel(const float* __restrict__ feat) {
    __shared__ float tile[32][33];
    int b  = blockIdx.z;
    int n0 = blockIdx.x * 32;
    int c0 = blockIdx.y * 32;
    int tx = threadIdx.x & 7;       // n-direction float4 index (8)
    int ty = threadIdx.x >> 3;      // c row (32)
    float4 v = *(const float4*)&feat[((size_t)(b * CC + c0 + ty)) * NN + n0 + tx * 4];
    tile[ty][tx * 4 + 0] = v.x;
    tile[ty][tx * 4 + 1] = v.y;
    tile[ty][tx * 4 + 2] = v.z;
    tile[ty][tx * 4 + 3] = v.w;
    __syncthreads();
    float4 w4;
    w4.x = tile[tx * 4 + 0][ty];
    w4.y = tile[tx * 4 + 1][ty];
    w4.z = tile[tx * 4 + 2][ty];
    w4.w = tile[tx * 4 + 3][ty];
    *(float4*)&g_featT[((size_t)b * NN + n0 + ty) * CC + c0 + tx * 4] = w4;
}

// ---------------- K2: ball query (ballot-free, bitmask + prefix) ----------------
// 8 warps/block, 4 centroids/warp. Lane w owns points [tile+32w, tile+32w+32):
// builds a 32-bit hit mask via predicated ORs (no votes), then a shfl prefix-sum
// over popc + ffs extraction emits first-32 indices in exact scan order.
#define BQ_M 4
#define BQ_WARPS 8
#define BQ_CPB (BQ_WARPS * BQ_M)   // 32 centroids per block
#define TILE_PTS 1024
#define TILE_PAIRS 512

__device__ __forceinline__ int swz(int p) {        // bank swizzle for u64 pair index
    return (p & ~15) | ((p ^ (p >> 4)) & 15);
}

__global__ __launch_bounds__(256) void bq_kernel(const float* __restrict__ xyz,
                                                 const float* __restrict__ new_xyz,
                                                 const int* __restrict__ fps_idx) {
    __shared__ u64 sx[TILE_PAIRS], sy[TILE_PAIRS], sz[TILE_PAIRS];
    __shared__ int slist[BQ_CPB][NS];

    int tid    = threadIdx.x;
    int warpId = tid >> 5;
    int lane   = tid & 31;
    int cbase  = blockIdx.x * BQ_CPB + warpId * BQ_M;
    int b      = (blockIdx.x * BQ_CPB) / NP;        // uniform per block

    u64 qx2[BQ_M], qy2[BQ_M], qz2[BQ_M];
    int cnt[BQ_M];
    #pragma unroll
    for (int c = 0; c < BQ_M; c++) {
        const float* q = new_xyz + (size_t)(cbase + c) * 3;
        float qx = q[0], qy = q[1], qz = q[2];
        qx2[c] = pk2(qx, qx); qy2[c] = pk2(qy, qy); qz2[c] = pk2(qz, qz);
        cnt[c] = 0;
    }

    const float* xb = xyz + (size_t)b * NN * 3;

    for (int tile = 0; tile < NN / TILE_PTS; tile++) {
        int tilebase = tile * TILE_PTS;
        // stage 1024 points (3072 floats), negated, deinterleaved, bank-swizzled
        #pragma unroll
        for (int j = 0; j < 12; j++) {
            int f = j * 256 + tid;                  // 0..3071
            float v = xb[tilebase * 3 + f];
            int pt = f / 3;
            int d  = f - pt * 3;
            int fi = swz(pt >> 1) * 2 + (pt & 1);
            float* dst = (d == 0) ? (float*)sx : (d == 1) ? (float*)sy : (float*)sz;
            dst[fi] = -v;
        }
        __syncthreads();

        bool active = (cnt[0] < NS) | (cnt[1] < NS) | (cnt[2] < NS) | (cnt[3] < NS);
        if (active) {
            unsigned mk[BQ_M] = {0u, 0u, 0u, 0u};
            #pragma unroll 4
            for (int k = 0; k < 16; k++) {
                int ph = swz(lane * 16 + k);
                u64 px = sx[ph], py = sy[ph], pz = sz[ph];
                #pragma unroll
                for (int c = 0; c < BQ_M; c++) {
                    u64 dx = addx2(qx2[c], px);     // q - p (points pre-negated)
                    u64 dy = addx2(qy2[c], py);
                    u64 dz = addx2(qz2[c], pz);
                    u64 d2 = fmax2(dx, dx, fmax2(dy, dy, mulx2(dz, dz)));
                    float d0, d1; upk2(d2, d0, d1);
                    mk[c] |= (d0 < R2) ? (1u << (2 * k)) : 0u;
                    mk[c] |= (d1 < R2) ? (2u << (2 * k)) : 0u;
                }
            }
            // compaction: scan-order emit (lanes ascend = points ascend)
            #pragma unroll
            for (int c = 0; c < BQ_M; c++) {
                unsigned m = mk[c];
                int pc = __popc(m);
                int incl = pc;
                #pragma unroll
                for (int o = 1; o < 32; o <<= 1) {
                    int v = __shfl_up_sync(0xffffffffu, incl, o);
                    if (lane >= o) incl += v;
                }
                int total = __shfl_sync(0xffffffffu, incl, 31);
                int base = cnt[c] + incl - pc;
                if (m && base < NS) {
                    int room = NS - base;
                    if (room > pc) room = pc;
                    int pbase = tilebase + lane * 32;
                    int cid = warpId * BQ_M + c;
                    for (int i = 0; i < room; i++) {
                        int bpos = __ffs(m) - 1;
                        m &= m - 1;
                        slist[cid][base + i] = pbase + bpos;
                    }
                }
                cnt[c] += total;
            }
        }
        __syncthreads();
    }

    __syncwarp();
    #pragma unroll
    for (int c = 0; c < BQ_M; c++) {
        int cid = warpId * BQ_M + c;
        int ci  = cbase + c;
        int cn  = cnt[c] < NS ? cnt[c] : NS;
        int base = ci * NSLOT;
        if (lane == 0) g_idx[base] = fps_idx[ci];
        int pad = (cn > 0) ? slist[cid][0] : 0;
        int v = (lane < cn) ? slist[cid][lane] : pad;
        g_idx[base + 1 + lane] = v;
    }
}

// ---------------- K3: gather + write output ----------------
__global__ __launch_bounds__(256) void group_kernel(const float* __restrict__ xyz,
                                                    const float* __restrict__ new_xyz,
                                                    float* __restrict__ out) {
    __shared__ float sfeat[64][65];
    __shared__ int   sidx[64];
    __shared__ float scent[3][64];

    int b  = blockIdx.y;
    int g0 = blockIdx.x * 64;
    int t  = threadIdx.x;

    if (t < 64) sidx[t] = g_idx[b * GPB + g0 + t];
    __syncthreads();

    if (t < 192) {   // 64 slots x 3 dims: centered xyz
        int s = t & 63, dim = t >> 6;
        int g = g0 + s;
        int p = g / NSLOT;
        int pi = sidx[s];
        scent[dim][s] = xyz[((size_t)b * NN + pi) * 3 + dim]
                      - new_xyz[((size_t)b * NP + p) * 3 + dim];
    }
    {   // feature gather: 4 threads per slot, 4x float4 each (256B contiguous per slot)
        int slot = t >> 2, part = t & 3;
        int pi = sidx[slot];
        const float4* src = (const float4*)(g_featT + ((size_t)b * NN + pi) * CC) + part * 4;
        #pragma unroll
        for (int k = 0; k < 4; k++) {
            float4 v = src[k];
            int cb = part * 16 + k * 4;
            sfeat[slot][cb + 0] = v.x;
            sfeat[slot][cb + 1] = v.y;
            sfeat[slot][cb + 2] = v.z;
            sfeat[slot][cb + 3] = v.w;
        }
    }
    __syncthreads();

    int s  = t & 63;
    int c0 = t >> 6;   // warp-uniform channel phase (0..3)
    size_t outb = (size_t)b * 70 * GPB + g0 + s;
    for (int cc = c0; cc < 70; cc += 4) {
        float v;
        if (cc < 6) v = scent[(cc < 3) ? cc : (cc - 3)][s];
        else        v = sfeat[s][cc - 6];
        out[outb + (size_t)cc * GPB] = v;
    }
}

// ---------------- launch ----------------
extern "C" void kernel_launch(void* const* d_in, const int* in_sizes, int n_in,
                              void* d_out, int out_size) {
    const float* xyz = nullptr;
    const float* new_xyz = nullptr;
    const float* features = nullptr;
    const int*   fps = nullptr;
    for (int i = 0; i < n_in; i++) {
        switch (in_sizes[i]) {
            case BB * NN * 3:  xyz      = (const float*)d_in[i]; break;
            case BB * NP * 3:  new_xyz  = (const float*)d_in[i]; break;
            case BB * CC * NN: features = (const float*)d_in[i]; break;
            case BB * NP:      fps      = (const int*)d_in[i];   break;
        }
    }
    transpose_kernel<<<dim3(NN / 32, CC / 32, BB), dim3(256)>>>(features);
    bq_kernel<<<(BB * NP) / BQ_CPB, 256>>>(xyz, new_xyz, fps);
    group_kernel<<<dim3(GPB / 64, BB), 256>>>(xyz, new_xyz, (float*)d_out);
}

// round 5
// speedup vs baseline: 1.4515x; 1.0315x over previous
#include <cuda_runtime.h>
#include <cstdint>

#define BB 4
#define NN 8192
#define NP 2048
#define CC 64
#define NS 32
#define R2 0.01f
#define NSLOT 33
#define GPB (NP * NSLOT)   // 67584 group-slots per batch

// Scratch (no cudaMalloc allowed)
__device__ float g_featT[BB * NN * CC];    // features transposed to (B, N, C)
__device__ int   g_idx[BB * NP * NSLOT];   // ball-query result incl. fps slot

typedef unsigned long long u64;

// ---------------- packed f32x2 helpers ----------------
__device__ __forceinline__ u64 pk2(float lo, float hi) {
    u64 r; asm("mov.b64 %0, {%1, %2};" : "=l"(r) : "f"(lo), "f"(hi)); return r;
}
__device__ __forceinline__ void upk2(u64 v, float& lo, float& hi) {
    asm("mov.b64 {%0, %1}, %2;" : "=f"(lo), "=f"(hi) : "l"(v));
}
__device__ __forceinline__ u64 addx2(u64 a, u64 b) {
    u64 r; asm("add.rn.f32x2 %0, %1, %2;" : "=l"(r) : "l"(a), "l"(b)); return r;
}
__device__ __forceinline__ u64 mulx2(u64 a, u64 b) {
    u64 r; asm("mul.rn.f32x2 %0, %1, %2;" : "=l"(r) : "l"(a), "l"(b)); return r;
}
__device__ __forceinline__ u64 fmax2(u64 a, u64 b, u64 c) {
    u64 r; asm("fma.rn.f32x2 %0, %1, %2, %3;" : "=l"(r) : "l"(a), "l"(b), "l"(c)); return r;
}

// ---------------- K1: transpose (B,C,N)->(B,N,C), 64x64 tile, ILP-4 float4 ----
__global__ __launch_bounds__(256) void transpose_kernel(const float* __restrict__ feat) {
    __shared__ float tile[64][65];
    int b  = blockIdx.z;
    int n0 = blockIdx.x * 64;
    int cx = threadIdx.x & 15;      // 16 float4 across n
    int cy = threadIdx.x >> 4;      // 16 c rows per pass
    float4 v[4];
    #pragma unroll
    for (int r = 0; r < 4; r++)
        v[r] = *(const float4*)&feat[((size_t)(b * CC + cy + r * 16)) * NN + n0 + cx * 4];
    #pragma unroll
    for (int r = 0; r < 4; r++) {
        tile[cy + r * 16][cx * 4 + 0] = v[r].x;
        tile[cy + r * 16][cx * 4 + 1] = v[r].y;
        tile[cy + r * 16][cx * 4 + 2] = v[r].z;
        tile[cy + r * 16][cx * 4 + 3] = v[r].w;
    }
    __syncthreads();
    #pragma unroll
    for (int r = 0; r < 4; r++) {
        int ny = cy + r * 16;
        float4 w;
        w.x = tile[cx * 4 + 0][ny];
        w.y = tile[cx * 4 + 1][ny];
        w.z = tile[cx * 4 + 2][ny];
        w.w = tile[cx * 4 + 3][ny];
        *(float4*)&g_featT[((size_t)b * NN + n0 + ny) * CC + cx * 4] = w;
    }
}

// ---------------- K2: ball query (ballot-free, bitmask + packed prefix) -------
// 8 warps/block, 4 centroids/warp. Lane w owns points [tile+32w, tile+32w+32):
// builds 32-bit hit masks via predicated ORs (no votes); two 16-bit-packed shfl
// prefix chains (2 centroids each) + ffs extraction emit first-32 in scan order.
#define BQ_M 4
#define BQ_WARPS 8
#define BQ_CPB (BQ_WARPS * BQ_M)   // 32 centroids per block
#define TILE_PTS 1024
#define TILE_PAIRS 512

__device__ __forceinline__ int swz(int p) {        // bank swizzle for u64 pair index
    return (p & ~15) | ((p ^ (p >> 4)) & 15);
}

__global__ __launch_bounds__(256) void bq_kernel(const float* __restrict__ xyz,
                                                 const float* __restrict__ new_xyz,
                                                 const int* __restrict__ fps_idx) {
    __shared__ u64 sx[TILE_PAIRS], sy[TILE_PAIRS], sz[TILE_PAIRS];
    __shared__ int slist[BQ_CPB][NS];

    int tid    = threadIdx.x;
    int warpId = tid >> 5;
    int lane   = tid & 31;
    int cbase  = blockIdx.x * BQ_CPB + warpId * BQ_M;
    int b      = (blockIdx.x * BQ_CPB) / NP;        // uniform per block

    u64 qx2[BQ_M], qy2[BQ_M], qz2[BQ_M];
    int cnt[BQ_M];
    #pragma unroll
    for (int c = 0; c < BQ_M; c++) {
        const float* q = new_xyz + (size_t)(cbase + c) * 3;
        float qx = q[0], qy = q[1], qz = q[2];
        qx2[c] = pk2(qx, qx); qy2[c] = pk2(qy, qy); qz2[c] = pk2(qz, qz);
        cnt[c] = 0;
    }

    const float* xb = xyz + (size_t)b * NN * 3;

    for (int tile = 0; tile < NN / TILE_PTS; tile++) {
        int tilebase = tile * TILE_PTS;
        // stage 1024 points (3072 floats) via 3x LDG.128, negated, swizzled
        #pragma unroll
        for (int j = 0; j < 3; j++) {
            int f0 = (j * 256 + tid) * 4;
            float4 v = *(const float4*)&xb[tilebase * 3 + f0];
            #pragma unroll
            for (int q = 0; q < 4; q++) {
                int f  = f0 + q;
                float val = (q == 0) ? v.x : (q == 1) ? v.y : (q == 2) ? v.z : v.w;
                int pt = f / 3;
                int d  = f - pt * 3;
                int fi = swz(pt >> 1) * 2 + (pt & 1);
                float* dst = (d == 0) ? (float*)sx : (d == 1) ? (float*)sy : (float*)sz;
                dst[fi] = -val;
            }
        }
        __syncthreads();

        bool active = (cnt[0] < NS) | (cnt[1] < NS) | (cnt[2] < NS) | (cnt[3] < NS);
        if (active) {
            unsigned mk[BQ_M] = {0u, 0u, 0u, 0u};
            #pragma unroll 4
            for (int k = 0; k < 16; k++) {
                int ph = swz(lane * 16 + k);
                u64 px = sx[ph], py = sy[ph], pz = sz[ph];
                #pragma unroll
                for (int c = 0; c < BQ_M; c++) {
                    u64 dx = addx2(qx2[c], px);     // q - p (points pre-negated)
                    u64 dy = addx2(qy2[c], py);
                    u64 dz = addx2(qz2[c], pz);
                    u64 d2 = fmax2(dx, dx, fmax2(dy, dy, mulx2(dz, dz)));
                    float d0, d1; upk2(d2, d0, d1);
                    mk[c] |= (d0 < R2) ? (1u << (2 * k)) : 0u;
                    mk[c] |= (d1 < R2) ? (2u << (2 * k)) : 0u;
                }
            }
            // packed prefix: counts for 2 centroids in 16-bit halves, 2 chains ILP
            int pc[BQ_M];
            #pragma unroll
            for (int c = 0; c < BQ_M; c++) pc[c] = __popc(mk[c]);
            unsigned a0 = (unsigned)pc[0] | ((unsigned)pc[1] << 16);
            unsigned a1 = (unsigned)pc[2] | ((unsigned)pc[3] << 16);
            unsigned i0 = a0, i1 = a1;
            #pragma unroll
            for (int o = 1; o < 32; o <<= 1) {
                unsigned v0 = __shfl_up_sync(0xffffffffu, i0, o);
                unsigned v1 = __shfl_up_sync(0xffffffffu, i1, o);
                if (lane >= o) { i0 += v0; i1 += v1; }
            }
            unsigned t0 = __shfl_sync(0xffffffffu, i0, 31);
            unsigned t1 = __shfl_sync(0xffffffffu, i1, 31);
            int incl[BQ_M]  = { (int)(i0 & 0xffffu), (int)(i0 >> 16),
                                (int)(i1 & 0xffffu), (int)(i1 >> 16) };
            int total[BQ_M] = { (int)(t0 & 0xffffu), (int)(t0 >> 16),
                                (int)(t1 & 0xffffu), (int)(t1 >> 16) };
            #pragma unroll
            for (int c = 0; c < BQ_M; c++) {
                unsigned m = mk[c];
                int base = cnt[c] + incl[c] - pc[c];
                if (m && base < NS) {
                    int room = NS - base;
                    if (room > pc[c]) room = pc[c];
                    int pbase = tilebase + lane * 32;
                    int cid = warpId * BQ_M + c;
                    for (int i = 0; i < room; i++) {
                        int bpos = __ffs(m) - 1;
                        m &= m - 1;
                        slist[cid][base + i] = pbase + bpos;
                    }
                }
                cnt[c] += total[c];
            }
        }
        __syncthreads();
    }

    __syncwarp();
    #pragma unroll
    for (int c = 0; c < BQ_M; c++) {
        int cid = warpId * BQ_M + c;
        int ci  = cbase + c;
        int cn  = cnt[c] < NS ? cnt[c] : NS;
        int base = ci * NSLOT;
        if (lane == 0) g_idx[base] = fps_idx[ci];
        int pad = (cn > 0) ? slist[cid][0] : 0;
        int v = (lane < cn) ? slist[cid][lane] : pad;
        g_idx[base + 1 + lane] = v;
    }
}

// ---------------- K3: gather + write output ----------------
__global__ __launch_bounds__(256) void group_kernel(const float* __restrict__ xyz,
                                                    const float* __restrict__ new_xyz,
                                                    float* __restrict__ out) {
    __shared__ float sfeat[64][65];
    __shared__ int   sidx[64];
    __shared__ float scent[3][64];

    int b  = blockIdx.y;
    int g0 = blockIdx.x * 64;
    int t  = threadIdx.x;

    if (t < 64) sidx[t] = g_idx[b * GPB + g0 + t];
    __syncthreads();

    if (t < 192) {   // 64 slots x 3 dims: centered xyz
        int s = t & 63, dim = t >> 6;
        int g = g0 + s;
        int p = g / NSLOT;
        int pi = sidx[s];
        scent[dim][s] = xyz[((size_t)b * NN + pi) * 3 + dim]
                      - new_xyz[((size_t)b * NP + p) * 3 + dim];
    }
    {   // feature gather: 4 threads per slot, 4x float4 each (256B contiguous per slot)
        int slot = t >> 2, part = t & 3;
        int pi = sidx[slot];
        const float4* src = (const float4*)(g_featT + ((size_t)b * NN + pi) * CC) + part * 4;
        #pragma unroll
        for (int k = 0; k < 4; k++) {
            float4 v = src[k];
            int cb = part * 16 + k * 4;
            sfeat[slot][cb + 0] = v.x;
            sfeat[slot][cb + 1] = v.y;
            sfeat[slot][cb + 2] = v.z;
            sfeat[slot][cb + 3] = v.w;
        }
    }
    __syncthreads();

    int s  = t & 63;
    int c0 = t >> 6;   // warp-uniform channel phase (0..3)
    size_t outb = (size_t)b * 70 * GPB + g0 + s;
    for (int cc = c0; cc < 70; cc += 4) {
        float v;
        if (cc < 6) v = scent[(cc < 3) ? cc : (cc - 3)][s];
        else        v = sfeat[s][cc - 6];
        out[outb + (size_t)cc * GPB] = v;
    }
}

// ---------------- launch (bq FIRST so the fixed ncu capture slot profiles it) --
extern "C" void kernel_launch(void* const* d_in, const int* in_sizes, int n_in,
                              void* d_out, int out_size) {
    const float* xyz = nullptr;
    const float* new_xyz = nullptr;
    const float* features = nullptr;
    const int*   fps = nullptr;
    for (int i = 0; i < n_in; i++) {
        switch (in_sizes[i]) {
            case BB * NN * 3:  xyz      = (const float*)d_in[i]; break;
            case BB * NP * 3:  new_xyz  = (const float*)d_in[i]; break;
            case BB * CC * NN: features = (const float*)d_in[i]; break;
            case BB * NP:      fps      = (const int*)d_in[i];   break;
        }
    }
    bq_kernel<<<(BB * NP) / BQ_CPB, 256>>>(xyz, new_xyz, fps);
    transpose_kernel<<<dim3(NN / 64, 1, BB), dim3(256)>>>(features);
    group_kernel<<<dim3(GPB / 64, BB), 256>>>(xyz, new_xyz, (float*)d_out);
}

// round 10
// speedup vs baseline: 1.6182x; 1.1148x over previous
#include <cuda_runtime.h>
#include <cstdint>

#define BB 4
#define NN 8192
#define NP 2048
#define CC 64
#define NS 32
#define R2 0.01f
#define NSLOT 33
#define GPB (NP * NSLOT)   // 67584 group-slots per batch
#define SEGS 2             // point-dimension split for bq parallelism

// Scratch (no cudaMalloc allowed)
__device__ float g_featT[BB * NN * CC];          // features transposed to (B, N, C)
__device__ int   g_pidx[BB * NP * SEGS * NS];    // per-segment partial neighbor lists
__device__ int   g_pcnt[BB * NP * SEGS];         // per-segment counts (clamped to NS)

typedef unsigned long long u64;

// ---------------- packed f32x2 helpers ----------------
__device__ __forceinline__ u64 pk2(float lo, float hi) {
    u64 r; asm("mov.b64 %0, {%1, %2};" : "=l"(r) : "f"(lo), "f"(hi)); return r;
}
__device__ __forceinline__ void upk2(u64 v, float& lo, float& hi) {
    asm("mov.b64 {%0, %1}, %2;" : "=f"(lo), "=f"(hi) : "l"(v));
}
__device__ __forceinline__ u64 addx2(u64 a, u64 b) {
    u64 r; asm("add.rn.f32x2 %0, %1, %2;" : "=l"(r) : "l"(a), "l"(b)); return r;
}
__device__ __forceinline__ u64 mulx2(u64 a, u64 b) {
    u64 r; asm("mul.rn.f32x2 %0, %1, %2;" : "=l"(r) : "l"(a), "l"(b)); return r;
}
__device__ __forceinline__ u64 fmax2(u64 a, u64 b, u64 c) {
    u64 r; asm("fma.rn.f32x2 %0, %1, %2, %3;" : "=l"(r) : "l"(a), "l"(b), "l"(c)); return r;
}

#define BQ_M 4
#define BQ_WARPS 8
#define BQ_CPB (BQ_WARPS * BQ_M)   // 32 centroids per block
#define TILE_PTS 1024
#define TILE_PAIRS 512
#define SEG_TILES ((NN / TILE_PTS) / SEGS)          // 4 tiles per segment
#define NBQ ((BB * NP / BQ_CPB) * SEGS)             // 512 bq blocks
#define NTR (BB * (NN / 64))                        // 512 transpose blocks

__device__ __forceinline__ int swz(int p) {        // bank swizzle for u64 pair index
    return (p & ~15) | ((p ^ (p >> 4)) & 15);
}

// ---------------- fused K1: ball query blocks + transpose blocks ----------------
__global__ __launch_bounds__(256) void fused_kernel(const float* __restrict__ xyz,
                                                    const float* __restrict__ new_xyz,
                                                    const float* __restrict__ feat) {
    __shared__ __align__(16) char smem_raw[16640];   // max(bq 16384, transpose 16640)

    if (blockIdx.x < NBQ) {
        // ---- ball query part: 8 warps, 4 centroids/warp, one point segment ----
        u64* sx = (u64*)smem_raw;
        u64* sy = sx + TILE_PAIRS;
        u64* sz = sy + TILE_PAIRS;
        int (*slist)[NS] = (int(*)[NS])(smem_raw + 3 * TILE_PAIRS * 8);

        int tid    = threadIdx.x;
        int warpId = tid >> 5;
        int lane   = tid & 31;
        int cg     = blockIdx.x >> 1;          // centroid-group id (0..255)
        int seg    = blockIdx.x & 1;           // point segment (0..1)
        int cbase  = cg * BQ_CPB + warpId * BQ_M;
        int b      = (cg * BQ_CPB) / NP;       // uniform per block

        u64 qx2[BQ_M], qy2[BQ_M], qz2[BQ_M];
        int cnt[BQ_M];
        #pragma unroll
        for (int c = 0; c < BQ_M; c++) {
            const float* q = new_xyz + (size_t)(cbase + c) * 3;
            float qx = q[0], qy = q[1], qz = q[2];
            qx2[c] = pk2(qx, qx); qy2[c] = pk2(qy, qy); qz2[c] = pk2(qz, qz);
            cnt[c] = 0;
        }

        const float* xb = xyz + (size_t)b * NN * 3;

        for (int tile = seg * SEG_TILES; tile < (seg + 1) * SEG_TILES; tile++) {
            int tilebase = tile * TILE_PTS;
            // stage 1024 points (3072 floats) via 3x LDG.128, negated, swizzled
            #pragma unroll
            for (int j = 0; j < 3; j++) {
                int f0 = (j * 256 + tid) * 4;
                float4 v = *(const float4*)&xb[tilebase * 3 + f0];
                #pragma unroll
                for (int q = 0; q < 4; q++) {
                    int f  = f0 + q;
                    float val = (q == 0) ? v.x : (q == 1) ? v.y : (q == 2) ? v.z : v.w;
                    int pt = f / 3;
                    int d  = f - pt * 3;
                    int fi = swz(pt >> 1) * 2 + (pt & 1);
                    float* dst = (d == 0) ? (float*)sx : (d == 1) ? (float*)sy : (float*)sz;
                    dst[fi] = -val;
                }
            }
            __syncthreads();

            bool active = (cnt[0] < NS) | (cnt[1] < NS) | (cnt[2] < NS) | (cnt[3] < NS);
            if (active) {
                unsigned mk[BQ_M] = {0u, 0u, 0u, 0u};
                #pragma unroll 4
                for (int k = 0; k < 16; k++) {
                    int ph = swz(lane * 16 + k);
                    u64 px = sx[ph], py = sy[ph], pz = sz[ph];
                    #pragma unroll
                    for (int c = 0; c < BQ_M; c++) {
                        u64 dx = addx2(qx2[c], px);     // q - p (points pre-negated)
                        u64 dy = addx2(qy2[c], py);
                        u64 dz = addx2(qz2[c], pz);
                        u64 d2 = fmax2(dx, dx, fmax2(dy, dy, mulx2(dz, dz)));
                        float d0, d1; upk2(d2, d0, d1);
                        mk[c] |= (d0 < R2) ? (1u << (2 * k)) : 0u;
                        mk[c] |= (d1 < R2) ? (2u << (2 * k)) : 0u;
                    }
                }
                // packed prefix: counts for 2 centroids in 16-bit halves, 2 chains ILP
                int pc[BQ_M];
                #pragma unroll
                for (int c = 0; c < BQ_M; c++) pc[c] = __popc(mk[c]);
                unsigned i0 = (unsigned)pc[0] | ((unsigned)pc[1] << 16);
                unsigned i1 = (unsigned)pc[2] | ((unsigned)pc[3] << 16);
                #pragma unroll
                for (int o = 1; o < 32; o <<= 1) {
                    unsigned v0 = __shfl_up_sync(0xffffffffu, i0, o);
                    unsigned v1 = __shfl_up_sync(0xffffffffu, i1, o);
                    if (lane >= o) { i0 += v0; i1 += v1; }
                }
                unsigned t0 = __shfl_sync(0xffffffffu, i0, 31);
                unsigned t1 = __shfl_sync(0xffffffffu, i1, 31);
                int incl[BQ_M]  = { (int)(i0 & 0xffffu), (int)(i0 >> 16),
                                    (int)(i1 & 0xffffu), (int)(i1 >> 16) };
                int total[BQ_M] = { (int)(t0 & 0xffffu), (int)(t0 >> 16),
                                    (int)(t1 & 0xffffu), (int)(t1 >> 16) };
                #pragma unroll
                for (int c = 0; c < BQ_M; c++) {
                    unsigned m = mk[c];
                    int base = cnt[c] + incl[c] - pc[c];
                    if (m && base < NS) {
                        int room = NS - base;
                        if (room > pc[c]) room = pc[c];
                        int pbase = tilebase + lane * 32;
                        int cid = warpId * BQ_M + c;
                        for (int i = 0; i < room; i++) {
                            int bpos = __ffs(m) - 1;
                            m &= m - 1;
                            slist[cid][base + i] = pbase + bpos;
                        }
                    }
                    cnt[c] += total[c];
                }
            }
            __syncthreads();
        }

        __syncwarp();
        #pragma unroll
        for (int c = 0; c < BQ_M; c++) {
            int cid = warpId * BQ_M + c;
            int ci  = cbase + c;
            int cn  = cnt[c] < NS ? cnt[c] : NS;
            if (lane == 0) g_pcnt[ci * SEGS + seg] = cn;
            if (lane < cn) g_pidx[(ci * SEGS + seg) * NS + lane] = slist[cid][lane];
        }
    } else {
        // ---- transpose part: (B,C,N)->(B,N,C), 64x64 tile, ILP-4 float4 ----
        float (*tile)[65] = (float(*)[65])smem_raw;
        int tb = blockIdx.x - NBQ;
        int b  = tb >> 7;
        int n0 = (tb & 127) * 64;
        int cx = threadIdx.x & 15;      // 16 float4 across n
        int cy = threadIdx.x >> 4;      // 16 c rows per pass
        float4 v[4];
        #pragma unroll
        for (int r = 0; r < 4; r++)
            v[r] = *(const float4*)&feat[((size_t)(b * CC + cy + r * 16)) * NN + n0 + cx * 4];
        #pragma unroll
        for (int r = 0; r < 4; r++) {
            tile[cy + r * 16][cx * 4 + 0] = v[r].x;
            tile[cy + r * 16][cx * 4 + 1] = v[r].y;
            tile[cy + r * 16][cx * 4 + 2] = v[r].z;
            tile[cy + r * 16][cx * 4 + 3] = v[r].w;
        }
        __syncthreads();
        #pragma unroll
        for (int r = 0; r < 4; r++) {
            int ny = cy + r * 16;
            float4 w;
            w.x = tile[cx * 4 + 0][ny];
            w.y = tile[cx * 4 + 1][ny];
            w.z = tile[cx * 4 + 2][ny];
            w.w = tile[cx * 4 + 3][ny];
            *(float4*)&g_featT[((size_t)b * NN + n0 + ny) * CC + cx * 4] = w;
        }
    }
}

// ---------------- K2: merge partial lists + gather + write output --------------
__global__ __launch_bounds__(256) void group_kernel(const float* __restrict__ xyz,
                                                    const float* __restrict__ new_xyz,
                                                    const int* __restrict__ fps_idx,
                                                    float* __restrict__ out) {
    __shared__ float sfeat[64][65];
    __shared__ int   sidx[64];
    __shared__ float scent[3][64];

    int b  = blockIdx.y;
    int g0 = blockIdx.x * 64;
    int t  = threadIdx.x;

    if (t < 64) {   // inline merge of 2 per-segment lists (scan-order concat, first 32)
        int gs = g0 + t;
        int p  = gs / NSLOT;
        int sl = gs - p * NSLOT;
        int ci = b * NP + p;
        int v;
        if (sl == 0) {
            v = fps_idx[ci];
        } else {
            int jj = sl - 1;
            int cA = g_pcnt[ci * SEGS + 0];
            int cB = g_pcnt[ci * SEGS + 1];
            const int* A = &g_pidx[(ci * SEGS + 0) * NS];
            const int* Bl = &g_pidx[(ci * SEGS + 1) * NS];
            if (jj < cA)            v = A[jj];
            else if (jj < cA + cB)  v = Bl[jj - cA];
            else                    v = (cA > 0) ? A[0] : ((cB > 0) ? Bl[0] : 0);
        }
        sidx[t] = v;
    }
    __syncthreads();

    if (t < 192) {   // 64 slots x 3 dims: centered xyz
        int s = t & 63, dim = t >> 6;
        int g = g0 + s;
        int p = g / NSLOT;
        int pi = sidx[s];
        scent[dim][s] = xyz[((size_t)b * NN + pi) * 3 + dim]
                      - new_xyz[((size_t)b * NP + p) * 3 + dim];
    }
    {   // feature gather: 4 threads per slot, 4x float4 each (256B contiguous per slot)
        int slot = t >> 2, part = t & 3;
        int pi = sidx[slot];
        const float4* src = (const float4*)(g_featT + ((size_t)b * NN + pi) * CC) + part * 4;
        #pragma unroll
        for (int k = 0; k < 4; k++) {
            float4 v = src[k];
            int cb = part * 16 + k * 4;
            sfeat[slot][cb + 0] = v.x;
            sfeat[slot][cb + 1] = v.y;
            sfeat[slot][cb + 2] = v.z;
            sfeat[slot][cb + 3] = v.w;
        }
    }
    __syncthreads();

    int s  = t & 63;
    int c0 = t >> 6;   // warp-uniform channel phase (0..3)
    size_t outb = (size_t)b * 70 * GPB + g0 + s;
    for (int cc = c0; cc < 70; cc += 4) {
        float v;
        if (cc < 6) v = scent[(cc < 3) ? cc : (cc - 3)][s];
        else        v = sfeat[s][cc - 6];
        out[outb + (size_t)cc * GPB] = v;
    }
}

// ---------------- launch ----------------
extern "C" void kernel_launch(void* const* d_in, const int* in_sizes, int n_in,
                              void* d_out, int out_size) {
    const float* xyz = nullptr;
    const float* new_xyz = nullptr;
    const float* features = nullptr;
    const int*   fps = nullptr;
    for (int i = 0; i < n_in; i++) {
        switch (in_sizes[i]) {
            case BB * NN * 3:  xyz      = (const float*)d_in[i]; break;
            case BB * NP * 3:  new_xyz  = (const float*)d_in[i]; break;
            case BB * CC * NN: features = (const float*)d_in[i]; break;
            case BB * NP:      fps      = (const int*)d_in[i];   break;
        }
    }
    fused_kernel<<<NBQ + NTR, 256>>>(xyz, new_xyz, features);
    group_kernel<<<dim3(GPB / 64, BB), 256>>>(xyz, new_xyz, fps, (float*)d_out);
}

// round 11
// speedup vs baseline: 1.8076x; 1.1171x over previous
#include <cuda_runtime.h>
#include <cstdint>

#define BB 4
#define NN 8192
#define NP 2048
#define CC 64
#define NS 32
#define R2 0.01f
#define NSLOT 33
#define GPB (NP * NSLOT)   // 67584 group-slots per batch
#define SEGS 2             // point-dimension split for bq parallelism

// Scratch (no cudaMalloc allowed)
__device__ float g_featT[BB * NN * CC];          // features transposed to (B, N, C)
__device__ int   g_pidx[BB * NP * SEGS * NS];    // per-segment partial neighbor lists
__device__ int   g_pcnt[BB * NP * SEGS];         // per-segment counts (clamped to NS)

typedef unsigned long long u64;

// ---------------- packed f32x2 helpers ----------------
__device__ __forceinline__ u64 pk2(float lo, float hi) {
    u64 r; asm("mov.b64 %0, {%1, %2};" : "=l"(r) : "f"(lo), "f"(hi)); return r;
}
__device__ __forceinline__ void upk2(u64 v, float& lo, float& hi) {
    asm("mov.b64 {%0, %1}, %2;" : "=f"(lo), "=f"(hi) : "l"(v));
}
__device__ __forceinline__ u64 addx2(u64 a, u64 b) {
    u64 r; asm("add.rn.f32x2 %0, %1, %2;" : "=l"(r) : "l"(a), "l"(b)); return r;
}
__device__ __forceinline__ u64 mulx2(u64 a, u64 b) {
    u64 r; asm("mul.rn.f32x2 %0, %1, %2;" : "=l"(r) : "l"(a), "l"(b)); return r;
}
__device__ __forceinline__ u64 fmax2(u64 a, u64 b, u64 c) {
    u64 r; asm("fma.rn.f32x2 %0, %1, %2, %3;" : "=l"(r) : "l"(a), "l"(b), "l"(c)); return r;
}

#define BQ_M 4
#define BQ_WARPS 8
#define BQ_CPB (BQ_WARPS * BQ_M)   // 32 centroids per block
#define TILE_PTS 1024
#define TILE_PAIRS 512
#define SEG_TILES ((NN / TILE_PTS) / SEGS)          // 4 tiles per segment
#define NBQ ((BB * NP / BQ_CPB) * SEGS)             // 512 bq blocks
#define NTR (BB * (NN / 64))                        // 512 transpose blocks

__device__ __forceinline__ int swz(int p) {        // bank swizzle for u64 pair index
    return (p & ~15) | ((p ^ (p >> 4)) & 15);
}

// ---------------- fused K1: ball query blocks + transpose blocks ----------------
__global__ __launch_bounds__(256) void fused_kernel(const float* __restrict__ xyz,
                                                    const float* __restrict__ new_xyz,
                                                    const float* __restrict__ feat) {
    __shared__ __align__(16) char smem_raw[16640];   // max(bq 16384, transpose 16640)

    if (blockIdx.x < NBQ) {
        // ---- ball query part: 8 warps, 4 centroids/warp, one point segment ----
        u64* sx = (u64*)smem_raw;
        u64* sy = sx + TILE_PAIRS;
        u64* sz = sy + TILE_PAIRS;
        int (*slist)[NS] = (int(*)[NS])(smem_raw + 3 * TILE_PAIRS * 8);

        int tid    = threadIdx.x;
        int warpId = tid >> 5;
        int lane   = tid & 31;
        int cg     = blockIdx.x >> 1;          // centroid-group id (0..255)
        int seg    = blockIdx.x & 1;           // point segment (0..1)
        int cbase  = cg * BQ_CPB + warpId * BQ_M;
        int b      = (cg * BQ_CPB) / NP;       // uniform per block

        u64 qx2[BQ_M], qy2[BQ_M], qz2[BQ_M];
        int cnt[BQ_M];
        #pragma unroll
        for (int c = 0; c < BQ_M; c++) {
            const float* q = new_xyz + (size_t)(cbase + c) * 3;
            float qx = q[0], qy = q[1], qz = q[2];
            qx2[c] = pk2(qx, qx); qy2[c] = pk2(qy, qy); qz2[c] = pk2(qz, qz);
            cnt[c] = 0;
        }

        const float* xb = xyz + (size_t)b * NN * 3;

        for (int tile = seg * SEG_TILES; tile < (seg + 1) * SEG_TILES; tile++) {
            int tilebase = tile * TILE_PTS;
            // stage 1024 points (3072 floats) via 3x LDG.128, negated, swizzled
            #pragma unroll
            for (int j = 0; j < 3; j++) {
                int f0 = (j * 256 + tid) * 4;
                float4 v = *(const float4*)&xb[tilebase * 3 + f0];
                #pragma unroll
                for (int q = 0; q < 4; q++) {
                    int f  = f0 + q;
                    float val = (q == 0) ? v.x : (q == 1) ? v.y : (q == 2) ? v.z : v.w;
                    int pt = f / 3;
                    int d  = f - pt * 3;
                    int fi = swz(pt >> 1) * 2 + (pt & 1);
                    float* dst = (d == 0) ? (float*)sx : (d == 1) ? (float*)sy : (float*)sz;
                    dst[fi] = -val;
                }
            }
            __syncthreads();

            bool active = (cnt[0] < NS) | (cnt[1] < NS) | (cnt[2] < NS) | (cnt[3] < NS);
            if (active) {
                unsigned mk[BQ_M] = {0u, 0u, 0u, 0u};
                #pragma unroll 4
                for (int k = 0; k < 16; k++) {
                    int ph = swz(lane * 16 + k);
                    u64 px = sx[ph], py = sy[ph], pz = sz[ph];
                    #pragma unroll
                    for (int c = 0; c < BQ_M; c++) {
                        u64 dx = addx2(qx2[c], px);     // q - p (points pre-negated)
                        u64 dy = addx2(qy2[c], py);
                        u64 dz = addx2(qz2[c], pz);
                        u64 d2 = fmax2(dx, dx, fmax2(dy, dy, mulx2(dz, dz)));
                        float d0, d1; upk2(d2, d0, d1);
                        mk[c] |= (d0 < R2) ? (1u << (2 * k)) : 0u;
                        mk[c] |= (d1 < R2) ? (2u << (2 * k)) : 0u;
                    }
                }
                // packed prefix: counts for 2 centroids in 16-bit halves, 2 chains ILP
                int pc[BQ_M];
                #pragma unroll
                for (int c = 0; c < BQ_M; c++) pc[c] = __popc(mk[c]);
                unsigned i0 = (unsigned)pc[0] | ((unsigned)pc[1] << 16);
                unsigned i1 = (unsigned)pc[2] | ((unsigned)pc[3] << 16);
                #pragma unroll
                for (int o = 1; o < 32; o <<= 1) {
                    unsigned v0 = __shfl_up_sync(0xffffffffu, i0, o);
                    unsigned v1 = __shfl_up_sync(0xffffffffu, i1, o);
                    if (lane >= o) { i0 += v0; i1 += v1; }
                }
                unsigned t0 = __shfl_sync(0xffffffffu, i0, 31);
                unsigned t1 = __shfl_sync(0xffffffffu, i1, 31);
                int incl[BQ_M]  = { (int)(i0 & 0xffffu), (int)(i0 >> 16),
                                    (int)(i1 & 0xffffu), (int)(i1 >> 16) };
                int total[BQ_M] = { (int)(t0 & 0xffffu), (int)(t0 >> 16),
                                    (int)(t1 & 0xffffu), (int)(t1 >> 16) };
                #pragma unroll
                for (int c = 0; c < BQ_M; c++) {
                    unsigned m = mk[c];
                    int base = cnt[c] + incl[c] - pc[c];
                    if (m && base < NS) {
                        int room = NS - base;
                        if (room > pc[c]) room = pc[c];
                        int pbase = tilebase + lane * 32;
                        int cid = warpId * BQ_M + c;
                        for (int i = 0; i < room; i++) {
                            int bpos = __ffs(m) - 1;
                            m &= m - 1;
                            slist[cid][base + i] = pbase + bpos;
                        }
                    }
                    cnt[c] += total[c];
                }
            }
            __syncthreads();
        }

        __syncwarp();
        #pragma unroll
        for (int c = 0; c < BQ_M; c++) {
            int cid = warpId * BQ_M + c;
            int ci  = cbase + c;
            int cn  = cnt[c] < NS ? cnt[c] : NS;
            if (lane == 0) g_pcnt[ci * SEGS + seg] = cn;
            if (lane < cn) g_pidx[(ci * SEGS + seg) * NS + lane] = slist[cid][lane];
        }
    } else {
        // ---- transpose part: (B,C,N)->(B,N,C), 64x64 tile, ILP-4 float4 ----
        float (*tile)[65] = (float(*)[65])smem_raw;
        int tb = blockIdx.x - NBQ;
        int b  = tb >> 7;
        int n0 = (tb & 127) * 64;
        int cx = threadIdx.x & 15;      // 16 float4 across n
        int cy = threadIdx.x >> 4;      // 16 c rows per pass
        float4 v[4];
        #pragma unroll
        for (int r = 0; r < 4; r++)
            v[r] = *(const float4*)&feat[((size_t)(b * CC + cy + r * 16)) * NN + n0 + cx * 4];
        #pragma unroll
        for (int r = 0; r < 4; r++) {
            tile[cy + r * 16][cx * 4 + 0] = v[r].x;
            tile[cy + r * 16][cx * 4 + 1] = v[r].y;
            tile[cy + r * 16][cx * 4 + 2] = v[r].z;
            tile[cy + r * 16][cx * 4 + 3] = v[r].w;
        }
        __syncthreads();
        #pragma unroll
        for (int r = 0; r < 4; r++) {
            int ny = cy + r * 16;
            float4 w;
            w.x = tile[cx * 4 + 0][ny];
            w.y = tile[cx * 4 + 1][ny];
            w.z = tile[cx * 4 + 2][ny];
            w.w = tile[cx * 4 + 3][ny];
            *(float4*)&g_featT[((size_t)b * NN + n0 + ny) * CC + cx * 4] = w;
        }
    }
}

// ---------------- K2: merge + warp-per-slot gather + branch-free output --------
__global__ __launch_bounds__(256) void group_kernel(const float* __restrict__ xyz,
                                                    const float* __restrict__ new_xyz,
                                                    const int* __restrict__ fps_idx,
                                                    float* __restrict__ out) {
    __shared__ float sfeat[64][65];
    __shared__ int   sidx[64];
    __shared__ float scent[3][65];

    int b  = blockIdx.y;
    int g0 = blockIdx.x * 64;
    int t  = threadIdx.x;

    if (t < 64) {   // inline merge of 2 per-segment lists (scan-order concat, first 32)
        int gs = g0 + t;
        int p  = gs / NSLOT;
        int sl = gs - p * NSLOT;
        int ci = b * NP + p;
        int v;
        if (sl == 0) {
            v = fps_idx[ci];
        } else {
            int jj = sl - 1;
            int cA = g_pcnt[ci * SEGS + 0];
            int cB = g_pcnt[ci * SEGS + 1];
            const int* A = &g_pidx[(ci * SEGS + 0) * NS];
            const int* Bl = &g_pidx[(ci * SEGS + 1) * NS];
            if (jj < cA)            v = A[jj];
            else if (jj < cA + cB)  v = Bl[jj - cA];
            else                    v = (cA > 0) ? A[0] : ((cB > 0) ? Bl[0] : 0);
        }
        sidx[t] = v;
    }
    __syncthreads();

    if (t < 192) {   // 64 slots x 3 dims: centered xyz
        int s = t & 63, dim = t >> 6;
        int g = g0 + s;
        int p = g / NSLOT;
        int pi = sidx[s];
        scent[dim][s] = xyz[((size_t)b * NN + pi) * 3 + dim]
                      - new_xyz[((size_t)b * NP + p) * 3 + dim];
    }
    {   // warp-per-slot feature gather: warp w loads rows for slots w*8..w*8+7.
        // Each LDG.64 covers a full contiguous 256B row across the warp ->
        // sector-perfect, 8 independent rows in flight (MLP-8).
        int w = t >> 5, L = t & 31;
        int base = w * 8;
        const float* fb = g_featT + (size_t)b * NN * CC;
        float2 v[8];
        #pragma unroll
        for (int j = 0; j < 8; j++) {
            int pi = sidx[base + j];            // LDS broadcast (warp-uniform addr)
            v[j] = *(const float2*)(fb + (size_t)pi * CC + 2 * L);
        }
        #pragma unroll
        for (int j = 0; j < 8; j++) {
            sfeat[base + j][2 * L]     = v[j].x;
            sfeat[base + j][2 * L + 1] = v[j].y;
        }
    }
    __syncthreads();

    int s  = t & 63;
    int c0 = t >> 6;   // warp-uniform channel phase (0..3)
    size_t outb = (size_t)b * 70 * GPB + g0 + s;

    // feature channels 6..69: exactly 16 uniform iterations, no predication
    {
        float* op = out + outb + (size_t)(6 + c0) * GPB;
        #pragma unroll
        for (int k = 0; k < 16; k++) {
            op[(size_t)(4 * k) * GPB] = sfeat[s][c0 + 4 * k];
        }
    }
    // xyz channels 0..5 (centered coords duplicated: cc and cc+3 identical)
    if (t < 192) {
        int dim = t >> 6;                        // 0..2
        float val = scent[dim][s];
        out[outb + (size_t)dim * GPB]       = val;
        out[outb + (size_t)(dim + 3) * GPB] = val;
    }
}

// ---------------- launch ----------------
extern "C" void kernel_launch(void* const* d_in, const int* in_sizes, int n_in,
                              void* d_out, int out_size) {
    const float* xyz = nullptr;
    const float* new_xyz = nullptr;
    const float* features = nullptr;
    const int*   fps = nullptr;
    for (int i = 0; i < n_in; i++) {
        switch (in_sizes[i]) {
            case BB * NN * 3:  xyz      = (const float*)d_in[i]; break;
            case BB * NP * 3:  new_xyz  = (const float*)d_in[i]; break;
            case BB * CC * NN: features = (const float*)d_in[i]; break;
            case BB * NP:      fps      = (const int*)d_in[i];   break;
        }
    }
    fused_kernel<<<NBQ + NTR, 256>>>(xyz, new_xyz, features);
    group_kernel<<<dim3(GPB / 64, BB), 256>>>(xyz, new_xyz, fps, (float*)d_out);
}